// round 17
// baseline (speedup 1.0000x reference)
#include <cuda_runtime.h>
#include <cuda_bf16.h>

#define B 2
#define N 8192
#define M 8192
#define D 64
#define KNN 16
#define QTOT (B * M)

#define BX 64                  // x-bins per batch
#define SUB 4                  // slab sub-splits (parallelism)
#define TCAP 768               // smem tile capacity (float4)
#define CAPT 16                // per-thread per-tile stack capacity (pow2)
#define SENT 3.4e38f
#define EPSF 5e-5f             // t-space filter margin
#define RPAD_EPS 1e-4f         // slab radius pad (>> fp noise)

// Scratch (allocation-free: __device__ globals)
__device__ float  g_f[B * N * D];
__device__ int    g_idx[B * M * KNN];
__device__ int    g_bcp[B * BX], g_bop[B * BX], g_bup[B * BX];  // point bins
__device__ int    g_bcq[B * BX], g_boq[B * BX], g_buq[B * BX];  // query bins
__device__ float4 g_px4[B * N];    // x-sorted points (x,y,z,0.5*|p|^2)
__device__ int    g_pid[B * N];
__device__ float4 g_qx4[B * M];    // x-sorted queries (x,y,z,|q|^2)
__device__ int    g_qid[B * M];
__device__ float  g_pd[B * M * SUB * KNN];
__device__ int    g_pi[B * M * SUB * KNN];
__device__ int    g_ovf[B * M * SUB];

__device__ __forceinline__ unsigned long long fma2(
    unsigned long long a, unsigned long long b, unsigned long long c) {
    unsigned long long r;
    asm("fma.rn.f32x2 %0, %1, %2, %3;" : "=l"(r) : "l"(a), "l"(b), "l"(c));
    return r;
}
__device__ __forceinline__ unsigned long long pack2(float lo, float hi) {
    unsigned long long r;
    asm("mov.b64 %0, {%1, %2};" : "=l"(r) : "f"(lo), "f"(hi));
    return r;
}
__device__ __forceinline__ void unpack2(unsigned long long v, float& lo, float& hi) {
    asm("mov.b64 {%0, %1}, %2;" : "=f"(lo), "=f"(hi) : "l"(v));
}

__device__ __forceinline__ int binf(float x) {
    int i = (int)(x * 64.0f);          // *64 is exact scaling; floor monotone
    return i < 0 ? 0 : (i > 63 ? 63 : i);
}

// Per-query radius^2 threshold covering ~TARGET points in expectation.
__device__ __forceinline__ float query_thresh(float qx, float qy, float qz) {
    const float TARGET = 48.0f;
    const float KVOL = (float)N * 4.18879f;
    float r = cbrtf(TARGET / KVOL);
#pragma unroll
    for (int it = 0; it < 3; it++) {
        float inv2r = 0.5f / r;
        float fx = (fminf(qx, r) + fminf(1.0f - qx, r)) * inv2r;
        float fy = (fminf(qy, r) + fminf(1.0f - qy, r)) * inv2r;
        float fz = (fminf(qz, r) + fminf(1.0f - qz, r)) * inv2r;
        float c = fmaxf(fx * fy * fz, 0.125f);
        r = cbrtf(TARGET / (KVOL * c));
    }
    return r * r;
}

// ---------------------------------------------------------------------------
// Kernel 1: f = feature1 @ Wp + bp (16 rows/block)
// ---------------------------------------------------------------------------
__global__ __launch_bounds__(256) void proj_kernel(
    const float* __restrict__ feat, const float* __restrict__ Wp,
    const float* __restrict__ bp)
{
    __shared__ float Ws[64 * 64];
    __shared__ float Fs[16][64];
    for (int i = threadIdx.x; i < 64 * 64; i += 256) Ws[i] = Wp[i];
    int r0 = blockIdx.x * 16;
    for (int i = threadIdx.x; i < 16 * 64; i += 256)
        Fs[i >> 6][i & 63] = feat[(r0 + (i >> 6)) * 64 + (i & 63)];
    __syncthreads();
    int rr = threadIdx.x >> 6;
    int c  = threadIdx.x & 63;
    float a0 = bp[c], a1 = a0, a2 = a0, a3 = a0;
#pragma unroll
    for (int d = 0; d < 64; d++) {
        float w = Ws[d * 64 + c];
        a0 = fmaf(Fs[rr     ][d], w, a0);
        a1 = fmaf(Fs[rr +  4][d], w, a1);
        a2 = fmaf(Fs[rr +  8][d], w, a2);
        a3 = fmaf(Fs[rr + 12][d], w, a3);
    }
    g_f[(r0 + rr     ) * 64 + c] = a0;
    g_f[(r0 + rr +  4) * 64 + c] = a1;
    g_f[(r0 + rr +  8) * 64 + c] = a2;
    g_f[(r0 + rr + 12) * 64 + c] = a3;
}

// ---------------------------------------------------------------------------
// 1-D x-binning: zero -> count -> scan -> scatter (points and queries)
// ---------------------------------------------------------------------------
__global__ void zero_kernel() {
    int t = threadIdx.x;
    if (t < B * BX) { g_bcp[t] = 0; g_bcq[t] = 0; }
}

__global__ void count_kernel(const float* __restrict__ xyz1,
                             const float* __restrict__ xyz2) {
    int t = blockIdx.x * blockDim.x + threadIdx.x;
    if (t < B * N) {
        int b = t >> 13;
        atomicAdd(&g_bcp[b * BX + binf(xyz1[t * 3])], 1);
    } else if (t < B * N + B * M) {
        int u = t - B * N;
        int b = u >> 13;
        atomicAdd(&g_bcq[b * BX + binf(xyz2[u * 3])], 1);
    }
}

__global__ __launch_bounds__(BX) void scan_bins_kernel() {
    __shared__ int s[BX];
    int b = blockIdx.x, t = threadIdx.x;
    s[t] = g_bcp[b * BX + t]; __syncthreads();
    for (int d = 1; d < BX; d <<= 1) {
        int v = s[t]; int w = (t >= d) ? s[t - d] : 0;
        __syncthreads(); s[t] = v + w; __syncthreads();
    }
    { int off = s[t] - g_bcp[b * BX + t];
      g_bop[b * BX + t] = off; g_bup[b * BX + t] = off; }
    __syncthreads();
    s[t] = g_bcq[b * BX + t]; __syncthreads();
    for (int d = 1; d < BX; d <<= 1) {
        int v = s[t]; int w = (t >= d) ? s[t - d] : 0;
        __syncthreads(); s[t] = v + w; __syncthreads();
    }
    { int off = s[t] - g_bcq[b * BX + t];
      g_boq[b * BX + t] = off; g_buq[b * BX + t] = off; }
}

__global__ void scatter_kernel(const float* __restrict__ xyz1,
                               const float* __restrict__ xyz2) {
    int t = blockIdx.x * blockDim.x + threadIdx.x;
    if (t < B * N) {
        int b = t >> 13;
        float x = xyz1[t * 3], y = xyz1[t * 3 + 1], z = xyz1[t * 3 + 2];
        int pos = atomicAdd(&g_bup[b * BX + binf(x)], 1);
        g_px4[b * N + pos] = make_float4(x, y, z, 0.5f * (x * x + y * y + z * z));
        g_pid[b * N + pos] = t & (N - 1);
    } else if (t < B * N + B * M) {
        int u = t - B * N;
        int b = u >> 13;
        float x = xyz2[u * 3], y = xyz2[u * 3 + 1], z = xyz2[u * 3 + 2];
        int pos = atomicAdd(&g_buq[b * BX + binf(x)], 1);
        g_qx4[b * M + pos] = make_float4(x, y, z, x * x + y * y + z * z);
        g_qid[b * M + pos] = u & (M - 1);
    }
}

// ---------------------------------------------------------------------------
// Kernel 2a: slab-limited filtered KNN.
// Block = 128 consecutive x-sorted queries; slab = [min(qx)-rpad, max(qx)+rpad]
// over the block (rpad = sqrt(T)+1e-4 per query, block-max). Any point with
// computed d < T lies within sqrt(T+2e-6) of its query's x -> inside the slab
// (pad 1e-4 >> 6e-6). Filter pass (t - halfw > u) <=> d < T + 2*EPSF, a
// superset of {d < T}; <16 passers or stack overflow -> merge full-scan
// fallback. Selection is lexicographic (d, index) == jax tie rule, so the
// (nondeterministic) scatter order cannot affect output.
// grid = (M/128, SUB, B), block = 128
// ---------------------------------------------------------------------------
__global__ __launch_bounds__(128) void knn_slab_kernel()
{
    __shared__ float4 tile[TCAP];       // 12KB
    __shared__ int    stk[CAPT][128];   // 8KB (slot-major: conflict-free)
    __shared__ float  red0[128], red1[128];
    int tid = threadIdx.x;
    int b   = blockIdx.z;
    int sB  = blockIdx.y;
    int qslot = b * M + blockIdx.x * 128 + tid;
    float4 q4 = g_qx4[qslot];
    float qx = q4.x, qy = q4.y, qz = q4.z, qs = q4.w;
    float T = query_thresh(qx, qy, qz);
    float rpad = sqrtf(T) + RPAD_EPS;

    red0[tid] = qx - rpad;
    red1[tid] = qx + rpad;
    __syncthreads();
    for (int st = 64; st > 0; st >>= 1) {
        if (tid < st) {
            red0[tid] = fminf(red0[tid], red0[tid + st]);
            red1[tid] = fmaxf(red1[tid], red1[tid + st]);
        }
        __syncthreads();
    }
    int lo = binf(red0[0]), hi = binf(red1[0]);
    int pstart = g_bop[b * BX + lo];
    int pend   = g_bop[b * BX + hi] + g_bcp[b * BX + hi];
    int total  = pend - pstart;
    int s0 = pstart + (int)(((long long)total * sB) / SUB);
    int s1 = pstart + (int)(((long long)total * (sB + 1)) / SUB);
    float u = 0.5f * (qs - T) - EPSF;

    float bd[KNN]; int bi[KNN];
#pragma unroll
    for (int j = 0; j < KNN; j++) { bd[j] = SENT; bi[j] = 0; }
    int ovf = 0;

    for (int pos = s0; pos < s1; pos += TCAP) {
        int nt = min(TCAP, s1 - pos);
        __syncthreads();                 // previous tile replay done
        for (int i = tid; i < nt; i += 128) tile[i] = g_px4[b * N + pos + i];
        __syncthreads();

        int cnt = 0;
#pragma unroll 4
        for (int jj = 0; jj < nt; jj++) {
            float4 p = tile[jj];
            float t = qx * p.x;
            t = fmaf(qy, p.y, t);
            t = fmaf(qz, p.z, t);
            bool pass = (t - p.w) > u;   // p.w = 0.5*|p|^2
            if (pass) stk[cnt & (CAPT - 1)][tid] = jj;
            cnt += pass;
        }
        ovf |= (cnt > CAPT);

        int kk = cnt < CAPT ? cnt : CAPT;
        for (int i = 0; i < kk; i++) {
            int jj = stk[i][tid];
            float4 p = tile[jj];
            float t = qx * p.x;
            t = fmaf(qy, p.y, t);
            t = fmaf(qz, p.z, t);
            float d = (qs + 2.0f * p.w) - 2.0f * t;   // 2*(0.5w) == w exactly
            int idx = g_pid[b * N + pos + jj];
            if (d < bd[KNN - 1] || (d == bd[KNN - 1] && idx < bi[KNN - 1])) {
                bd[KNN - 1] = d; bi[KNN - 1] = idx;
#pragma unroll
                for (int j = KNN - 1; j > 0; --j) {
                    if (bd[j] < bd[j - 1] ||
                        (bd[j] == bd[j - 1] && bi[j] < bi[j - 1])) {
                        float td = bd[j]; bd[j] = bd[j - 1]; bd[j - 1] = td;
                        int   ti = bi[j]; bi[j] = bi[j - 1]; bi[j - 1] = ti;
                    }
                }
            }
        }
    }

    size_t base = ((size_t)qslot * SUB + sB) * KNN;
#pragma unroll
    for (int j = 0; j < KNN; j++) { g_pd[base + j] = bd[j]; g_pi[base + j] = bi[j]; }
    g_ovf[(size_t)qslot * SUB + sB] = ovf;
}

// ---------------------------------------------------------------------------
// Kernel 2b: lexicographic SUB-way merge; full-scan fallback on sentinel/ovf.
// ---------------------------------------------------------------------------
__global__ __launch_bounds__(256) void knn_merge_kernel(
    const float* __restrict__ xyz1, float* __restrict__ outW)
{
    int slot = blockIdx.x * 256 + threadIdx.x;
    if (slot >= QTOT) return;
    int b = slot >> 13;
    size_t pb = (size_t)slot * SUB * KNN;

    int ovf = 0;
#pragma unroll
    for (int c = 0; c < SUB; c++) ovf |= g_ovf[(size_t)slot * SUB + c];

    int   ptr[SUB];
    float hd[SUB]; int hix[SUB];
#pragma unroll
    for (int c = 0; c < SUB; c++) {
        ptr[c] = 0;
        hd[c]  = g_pd[pb + c * KNN];
        hix[c] = g_pi[pb + c * KNN];
    }

    int outi[KNN];
    float first = SENT, last = SENT;
#pragma unroll
    for (int j = 0; j < KNN; j++) {
        int best = 0;
#pragma unroll
        for (int c = 1; c < SUB; c++)
            if (hd[c] < hd[best] || (hd[c] == hd[best] && hix[c] < hix[best]))
                best = c;
        outi[j] = hix[best];
        if (j == 0) first = hd[best];
        last = hd[best];
        ptr[best]++;
        if (ptr[best] < KNN) {
            hd[best]  = g_pd[pb + best * KNN + ptr[best]];
            hix[best] = g_pi[pb + best * KNN + ptr[best]];
        } else {
            hd[best] = SENT; hix[best] = 0x7fffffff;
        }
    }

    float4 q4 = g_qx4[slot];
    if (ovf || last >= SENT) {
        // fallback: full unfiltered scan, ascending-n strict-< (== lexicographic)
        float qx = q4.x, qy = q4.y, qz = q4.z, qs = q4.w;
        float bd[KNN];
#pragma unroll
        for (int j = 0; j < KNN; j++) { bd[j] = SENT; outi[j] = 0; }
        const float* base = xyz1 + (size_t)b * N * 3;
        for (int n = 0; n < N; n++) {
            float x = base[n * 3], y = base[n * 3 + 1], z = base[n * 3 + 2];
            float ps = x * x + y * y + z * z;
            float t = qx * x;
            t = fmaf(qy, y, t);
            t = fmaf(qz, z, t);
            float d = (qs + ps) - 2.0f * t;
            if (d < bd[KNN - 1]) {
                bd[KNN - 1] = d; outi[KNN - 1] = n;
#pragma unroll
                for (int j = KNN - 1; j > 0; --j) {
                    if (bd[j] < bd[j - 1]) {
                        float td = bd[j]; bd[j] = bd[j - 1]; bd[j - 1] = td;
                        int   ti = outi[j]; outi[j] = outi[j - 1]; outi[j - 1] = ti;
                    }
                }
            }
        }
        first = bd[0];
    }

    int qid = g_qid[slot];
    size_t qorig = (size_t)b * M + qid;
#pragma unroll
    for (int j = 0; j < KNN; j++) g_idx[qorig * KNN + j] = outi[j];
    outW[qorig] = (first > 0.03f) ? 10.0f : 1.0f;
}

// ---------------------------------------------------------------------------
// Kernel 3: gather + MLP + reduction — VERBATIM round-14/16 version (76us).
// ---------------------------------------------------------------------------
#define MLP_BLOCKS 1024
__global__ __launch_bounds__(128, 3) void mlp_kernel(
    const float* __restrict__ xyz1, const float* __restrict__ xyz2,
    const float* __restrict__ W1, const float* __restrict__ b1,
    const float* __restrict__ W2, const float* __restrict__ b2,
    float* __restrict__ out)
{
    __shared__ float Hs[4][KNN * 64];
    __shared__ float Gs[4][KNN * 64];
    int lane = threadIdx.x & 31;
    int wid  = threadIdx.x >> 5;
    int ca   = lane;
    int cb   = lane + 32;

    unsigned long long w2a[32], w2b[32];
#pragma unroll
    for (int i = 0; i < 32; i++) {
        w2a[i] = pack2(W2[(2 * i) * 64 + ca], W2[(2 * i + 1) * 64 + ca]);
        w2b[i] = pack2(W2[(2 * i) * 64 + cb], W2[(2 * i + 1) * 64 + cb]);
    }
    float w10a = W1[ca], w11a = W1[64 + ca], w12a = W1[128 + ca];
    float w10b = W1[cb], w11b = W1[64 + cb], w12b = W1[128 + cb];
    float b1a = b1[ca], b1b = b1[cb];
    float b2a = b2[ca], b2b = b2[cb];

    float* H = Hs[wid];
    float* G = Gs[wid];
    int gw = blockIdx.x * 4 + wid;

#pragma unroll 1
    for (int q = gw; q < QTOT; q += 4 * MLP_BLOCKS) {
        int b = q >> 13;
        int j16 = (lane < KNN) ? g_idx[(size_t)q * KNN + lane] : 0;
        float px = 0.0f, py = 0.0f, pz = 0.0f;
        if (lane < KNN) {
            const float* p = xyz1 + ((size_t)b * N + j16) * 3;
            px = p[0]; py = p[1]; pz = p[2];
        }
        const float* x2 = xyz2 + (size_t)q * 3;
        float qx = x2[0], qy = x2[1], qz = x2[2];
        const float* fb = g_f + (size_t)b * N * 64;

#pragma unroll 8
        for (int k = 0; k < KNN; k++) {
            float gx = __shfl_sync(0xffffffffu, px, k) - qx;
            float gy = __shfl_sync(0xffffffffu, py, k) - qy;
            float gz = __shfl_sync(0xffffffffu, pz, k) - qz;
            float ha = fmaf(gz, w12a, fmaf(gy, w11a, fmaf(gx, w10a, b1a)));
            float hb = fmaf(gz, w12b, fmaf(gy, w11b, fmaf(gx, w10b, b1b)));
            H[k * 64 + ca] = fmaxf(ha, 0.0f);
            H[k * 64 + cb] = fmaxf(hb, 0.0f);
        }
#pragma unroll 8
        for (int k = 0; k < KNN; k++) {
            int j = __shfl_sync(0xffffffffu, j16, k);
            G[k * 64 + ca] = fb[(size_t)j * 64 + ca];
            G[k * 64 + cb] = fb[(size_t)j * 64 + cb];
        }
        __syncwarp();

        float acca = 0.0f, accb = 0.0f;
#pragma unroll 1
        for (int k = 0; k < KNN; k++) {
            float gfa = G[k * 64 + ca];
            float gfb = G[k * 64 + cb];
            const ulonglong2* h2 = (const ulonglong2*)(H + k * 64);
            unsigned long long pa0 = 0ull, pa1 = 0ull, pb0 = 0ull, pb1 = 0ull;
#pragma unroll
            for (int i = 0; i < 16; i++) {
                ulonglong2 hv = h2[i];
                pa0 = fma2(hv.x, w2a[2 * i],     pa0);
                pa1 = fma2(hv.y, w2a[2 * i + 1], pa1);
                pb0 = fma2(hv.x, w2b[2 * i],     pb0);
                pb1 = fma2(hv.y, w2b[2 * i + 1], pb1);
            }
            float a0, a1, a2, a3, c0, c1, c2, c3;
            unpack2(pa0, a0, a1); unpack2(pa1, a2, a3);
            unpack2(pb0, c0, c1); unpack2(pb1, c2, c3);
            float pwa = b2a + ((a0 + a1) + (a2 + a3));
            float pwb = b2b + ((c0 + c1) + (c2 + c3));
            acca = fmaf(pwa, gfa, acca);
            accb = fmaf(pwb, gfb, accb);
        }
        out[(size_t)q * 64 + ca] = acca * 0.25f;
        out[(size_t)q * 64 + cb] = accb * 0.25f;
        __syncwarp();
    }
}

// ---------------------------------------------------------------------------
// launch
// ---------------------------------------------------------------------------
extern "C" void kernel_launch(void* const* d_in, const int* in_sizes, int n_in,
                              void* d_out, int out_size)
{
    const float* feature1 = (const float*)d_in[0];
    const float* xyz1     = (const float*)d_in[1];
    const float* xyz2     = (const float*)d_in[2];
    const float* Wp       = (const float*)d_in[3];
    const float* bp       = (const float*)d_in[4];
    const float* W1       = (const float*)d_in[5];
    const float* b1       = (const float*)d_in[6];
    const float* W2       = (const float*)d_in[7];
    const float* b2       = (const float*)d_in[8];

    float* out_feat = (float*)d_out;                       // [B*M*64]
    float* out_w    = (float*)d_out + (size_t)B * M * 64;  // [B*M]

    proj_kernel<<<(B * N) / 16, 256>>>(feature1, Wp, bp);

    zero_kernel<<<1, 128>>>();
    count_kernel<<<(B * (N + M) + 255) / 256, 256>>>(xyz1, xyz2);
    scan_bins_kernel<<<B, BX>>>();
    scatter_kernel<<<(B * (N + M) + 255) / 256, 256>>>(xyz1, xyz2);
    knn_slab_kernel<<<dim3(M / 128, SUB, B), 128>>>();
    knn_merge_kernel<<<(QTOT + 255) / 256, 256>>>(xyz1, out_w);

    mlp_kernel<<<MLP_BLOCKS, 128>>>(xyz1, xyz2, W1, b1, W2, b2, out_feat);
}